// round 1
// baseline (speedup 1.0000x reference)
#include <cuda_runtime.h>
#include <cstddef>

// Problem dims (fixed by the dataset)
#define Bn 8192
#define Dn 512
#define Hn 1024
#define KV 11
#define NV 12          // views = identity + KV transforms
#define NPAIR 78       // 12*13/2 unique pairs (incl. diagonal)
#define EPSF 1e-8f

// ---------------------------------------------------------------------------
// Scratch (device globals; no runtime allocation allowed)
// ---------------------------------------------------------------------------
__device__ float g_bufT[(size_t)NV * Bn * Dn];   // views: [12, B, D]   201 MB
__device__ float g_bufH[(size_t)NV * Bn * Hn];   // hidden: [12, B, H]  403 MB
__device__ float g_bufZ[(size_t)NV * Bn * Hn];   // encodings: [12,B,H] 403 MB

// ---------------------------------------------------------------------------
// Batched GEMM:  C[bz] = act(A[bz] @ W[bz] + bias[bz])
// A: [M,Kd] row-major, W: [Kd,N] row-major, bias: [N]
// ACT: 0 = none, 1 = tanh, 2 = relu
// Tiles: BM=BN=128, BK=16; 256 threads, 8x8 per thread.
// All dims here are multiples of the tile sizes (no bounds checks).
// ---------------------------------------------------------------------------
constexpr int BM = 128, BN = 128, BK = 16, TM = 8, TN = 8;

template <int ACT>
__global__ void __launch_bounds__(256, 2) gemm_bias_act(
    const float* __restrict__ A, const float* __restrict__ W,
    const float* __restrict__ bias, float* __restrict__ C,
    int M, int N, int Kd,
    size_t sA, size_t sW, size_t sBias, size_t sC)
{
    __shared__ float As[BK][BM];
    __shared__ float Ws[BK][BN];

    const int bz = blockIdx.z;
    A    += (size_t)bz * sA;
    W    += (size_t)bz * sW;
    bias += (size_t)bz * sBias;
    C    += (size_t)bz * sC;

    const int bm = blockIdx.y * BM;
    const int bn = blockIdx.x * BN;
    const int tid = threadIdx.x;

    // A tile loader: 128 rows x 16 cols, as float4 along K then transposed into As[k][m]
    const int arow  = tid >> 2;          // 0..63
    const int acol4 = (tid & 3) * 4;     // 0,4,8,12
    // W tile loader: 16 rows x 128 cols, float4 along N
    const int wrow = tid >> 5;           // 0..7
    const int wcol = (tid & 31) * 4;     // 0..124

    const int ty = tid >> 4;             // 0..15
    const int tx = tid & 15;             // 0..15

    float acc[TM][TN];
#pragma unroll
    for (int i = 0; i < TM; i++)
#pragma unroll
        for (int j = 0; j < TN; j++) acc[i][j] = 0.0f;

    for (int k0 = 0; k0 < Kd; k0 += BK) {
#pragma unroll
        for (int i = 0; i < 2; i++) {
            int r = arow + i * 64;
            float4 v = *(const float4*)(A + (size_t)(bm + r) * Kd + k0 + acol4);
            As[acol4 + 0][r] = v.x;
            As[acol4 + 1][r] = v.y;
            As[acol4 + 2][r] = v.z;
            As[acol4 + 3][r] = v.w;
        }
#pragma unroll
        for (int i = 0; i < 2; i++) {
            int r = wrow + i * 8;
            *(float4*)(&Ws[r][wcol]) =
                *(const float4*)(W + (size_t)(k0 + r) * N + bn + wcol);
        }
        __syncthreads();

#pragma unroll
        for (int kk = 0; kk < BK; kk++) {
            float ra[TM], rb[TN];
#pragma unroll
            for (int i = 0; i < TM; i += 4) {
                float4 v = *(const float4*)(&As[kk][ty * TM + i]);
                ra[i] = v.x; ra[i + 1] = v.y; ra[i + 2] = v.z; ra[i + 3] = v.w;
            }
#pragma unroll
            for (int j = 0; j < TN; j += 4) {
                float4 v = *(const float4*)(&Ws[kk][tx * TN + j]);
                rb[j] = v.x; rb[j + 1] = v.y; rb[j + 2] = v.z; rb[j + 3] = v.w;
            }
#pragma unroll
            for (int i = 0; i < TM; i++)
#pragma unroll
                for (int j = 0; j < TN; j++)
                    acc[i][j] = fmaf(ra[i], rb[j], acc[i][j]);
        }
        __syncthreads();
    }

    // Epilogue: bias + activation, vectorized stores
#pragma unroll
    for (int i = 0; i < TM; i++) {
        int row = bm + ty * TM + i;
#pragma unroll
        for (int j = 0; j < TN; j += 4) {
            int col = bn + tx * TN + j;
            float4 o;
            o.x = acc[i][j + 0] + bias[col + 0];
            o.y = acc[i][j + 1] + bias[col + 1];
            o.z = acc[i][j + 2] + bias[col + 2];
            o.w = acc[i][j + 3] + bias[col + 3];
            if (ACT == 1) {
                o.x = tanhf(o.x); o.y = tanhf(o.y);
                o.z = tanhf(o.z); o.w = tanhf(o.w);
            } else if (ACT == 2) {
                o.x = fmaxf(o.x, 0.f); o.y = fmaxf(o.y, 0.f);
                o.z = fmaxf(o.z, 0.f); o.w = fmaxf(o.w, 0.f);
            }
            *(float4*)(C + (size_t)row * N + col) = o;
        }
    }
}

// ---------------------------------------------------------------------------
// Gram + normalize + contrastive score, one block per batch row b.
// Computes G(i,j) = <Z_i[b], Z_j[b]> for all 12 views, then
// cos(i,j) = G(i,j) / (max(|Z_i|,eps) * max(|Z_j|,eps)), and
// out[b] = sum_{k=1..11} log((pos_k + neg_k)/pos_k),
//   pos_k = exp(cos(0,k)),  neg_k = sum_{l>=1, l!=k} exp(cos(k,l))
// ---------------------------------------------------------------------------
__device__ __forceinline__ void pair_of(int p, int& i, int& j) {
    int ii = 0, rem = p;
    while (rem >= NV - ii) { rem -= NV - ii; ii++; }
    i = ii; j = ii + rem;
}

#define CHUNK 256
#define MAXP_PER_WARP 10   // ceil(78/8)

__global__ void gram_score(const float* __restrict__ Z, float* __restrict__ out)
{
    __shared__ float chunk[NV][CHUNK];
    __shared__ float sG[NV * NV];

    const int b    = blockIdx.x;
    const int tid  = threadIdx.x;
    const int lane = tid & 31;
    const int warp = tid >> 5;   // 0..7

    // Precompute this warp's pair indices
    int pi_i[MAXP_PER_WARP], pi_j[MAXP_PER_WARP];
    float accp[MAXP_PER_WARP];
#pragma unroll
    for (int pi = 0; pi < MAXP_PER_WARP; pi++) {
        int p = warp + pi * 8;
        if (p < NPAIR) pair_of(p, pi_i[pi], pi_j[pi]);
        else { pi_i[pi] = 0; pi_j[pi] = 0; }
        accp[pi] = 0.0f;
    }

    for (int h0 = 0; h0 < Hn; h0 += CHUNK) {
        __syncthreads();
        // load 12 x CHUNK slab (float4-vectorized)
        for (int i = tid; i < NV * (CHUNK / 4); i += 256) {
            int v = i / (CHUNK / 4);
            int h4 = (i % (CHUNK / 4)) * 4;
            float4 val = *(const float4*)(Z + (size_t)v * Bn * Hn + (size_t)b * Hn + h0 + h4);
            *(float4*)(&chunk[v][h4]) = val;
        }
        __syncthreads();
#pragma unroll
        for (int pi = 0; pi < MAXP_PER_WARP; pi++) {
            int p = warp + pi * 8;
            if (p < NPAIR) {
                const float* ri = chunk[pi_i[pi]];
                const float* rj = chunk[pi_j[pi]];
                float s = 0.0f;
#pragma unroll
                for (int t = 0; t < CHUNK / 32; t++)
                    s = fmaf(ri[lane + 32 * t], rj[lane + 32 * t], s);
                accp[pi] += s;
            }
        }
    }

    // reduce each pair across the warp and publish symmetric G
#pragma unroll
    for (int pi = 0; pi < MAXP_PER_WARP; pi++) {
        int p = warp + pi * 8;
        if (p < NPAIR) {
            float s = accp[pi];
#pragma unroll
            for (int o = 16; o; o >>= 1) s += __shfl_xor_sync(0xffffffffu, s, o);
            if (lane == 0) {
                sG[pi_i[pi] * NV + pi_j[pi]] = s;
                sG[pi_j[pi] * NV + pi_i[pi]] = s;
            }
        }
    }
    __syncthreads();

    if (tid == 0) {
        float nm[NV];
#pragma unroll
        for (int i = 0; i < NV; i++)
            nm[i] = fmaxf(sqrtf(sG[i * NV + i]), EPSF);
        float total = 0.0f;
        for (int k = 1; k < NV; k++) {
            float pos = expf(sG[k] / (nm[0] * nm[k]));          // cos(z, z_k)
            float neg = 0.0f;
            for (int l = 1; l < NV; l++)
                if (l != k) neg += expf(sG[k * NV + l] / (nm[k] * nm[l]));
            total += logf((pos + neg) / pos);
        }
        out[b] = total;
    }
}

// ---------------------------------------------------------------------------
// Launch
// ---------------------------------------------------------------------------
extern "C" void kernel_launch(void* const* d_in, const int* in_sizes, int n_in,
                              void* d_out, int out_size)
{
    const float* x   = (const float*)d_in[0];
    const float* Wt1 = (const float*)d_in[1];
    const float* bt1 = (const float*)d_in[2];
    const float* Wt2 = (const float*)d_in[3];
    const float* bt2 = (const float*)d_in[4];
    const float* We1 = (const float*)d_in[5];
    const float* be1 = (const float*)d_in[6];
    const float* We2 = (const float*)d_in[7];
    const float* be2 = (const float*)d_in[8];
    float* out = (float*)d_out;

    float *bufT = nullptr, *bufH = nullptr, *bufZ = nullptr;
    cudaGetSymbolAddress((void**)&bufT, g_bufT);
    cudaGetSymbolAddress((void**)&bufH, g_bufH);
    cudaGetSymbolAddress((void**)&bufZ, g_bufZ);

    // view 0 = identity
    cudaMemcpyAsync(bufT, x, (size_t)Bn * Dn * sizeof(float),
                    cudaMemcpyDeviceToDevice);

    dim3 blk(256);

    // A1: bufH[k] = tanh(x @ Wt1[k] + bt1[k])        k = 0..10
    gemm_bias_act<1><<<dim3(Hn / BN, Bn / BM, KV), blk>>>(
        x, Wt1, bt1, bufH, Bn, Hn, Dn,
        (size_t)0, (size_t)Dn * Hn, (size_t)Hn, (size_t)Bn * Hn);

    // A2: bufT[1+k] = bufH[k] @ Wt2[k] + bt2[k]
    gemm_bias_act<0><<<dim3(Dn / BN, Bn / BM, KV), blk>>>(
        bufH, Wt2, bt2, bufT + (size_t)Bn * Dn, Bn, Dn, Hn,
        (size_t)Bn * Hn, (size_t)Hn * Dn, (size_t)Dn, (size_t)Bn * Dn);

    // B1: bufH[v] = relu(bufT[v] @ We1 + be1)        v = 0..11
    gemm_bias_act<2><<<dim3(Hn / BN, Bn / BM, NV), blk>>>(
        bufT, We1, be1, bufH, Bn, Hn, Dn,
        (size_t)Bn * Dn, (size_t)0, (size_t)0, (size_t)Bn * Hn);

    // B2: bufZ[v] = bufH[v] @ We2 + be2
    gemm_bias_act<0><<<dim3(Hn / BN, Bn / BM, NV), blk>>>(
        bufH, We2, be2, bufZ, Bn, Hn, Hn,
        (size_t)Bn * Hn, (size_t)0, (size_t)0, (size_t)Bn * Hn);

    // C: Gram + normalize + score
    gram_score<<<Bn, 256>>>(bufZ, out);
}

// round 3
// speedup vs baseline: 2.2535x; 2.2535x over previous
#include <cuda_runtime.h>
#include <cuda_bf16.h>
#include <cstddef>
#include <cstdint>

#define Bn 8192
#define Dn 512
#define Hn 1024
#define KV 11
#define NV 12
#define NPAIR 78
#define EPSF 1e-8f

// ---------------------------------------------------------------------------
// Device scratch.  Split-bf16 activations: [rows, 2*K] (hi | lo along K).
// Weights transposed+split: WT[n, 2*K].
// ---------------------------------------------------------------------------
__device__ __align__(1024) __nv_bfloat16 g_T[(size_t)NV * Bn * (2 * Dn)];
__device__ __align__(1024) __nv_bfloat16 g_H[(size_t)NV * Bn * (2 * Hn)];
__device__ __align__(1024) float        g_Z[(size_t)NV * Bn * Hn];
__device__ __align__(1024) __nv_bfloat16 g_WT1[(size_t)KV * Hn * (2 * Dn)];
__device__ __align__(1024) __nv_bfloat16 g_WT2[(size_t)KV * Dn * (2 * Hn)];
__device__ __align__(1024) __nv_bfloat16 g_WE1[(size_t)Hn * (2 * Dn)];
__device__ __align__(1024) __nv_bfloat16 g_WE2[(size_t)Hn * (2 * Hn)];

// ---------------------------------------------------------------------------
__device__ __forceinline__ uint32_t smem_u32(const void* p) {
    uint32_t a;
    asm("{ .reg .u64 t; cvta.to.shared.u64 t, %1; cvt.u32.u64 %0, t; }" : "=r"(a) : "l"(p));
    return a;
}
__device__ __forceinline__ void cpa16(uint32_t dst, const void* src) {
    asm volatile("cp.async.cg.shared.global [%0], [%1], 16;" :: "r"(dst), "l"(src) : "memory");
}
#define CP_COMMIT() asm volatile("cp.async.commit_group;" ::: "memory")
#define CP_WAIT2()  asm volatile("cp.async.wait_group 2;" ::: "memory")

__device__ __forceinline__ void ldm4(uint32_t* r, uint32_t addr) {
    asm volatile("ldmatrix.sync.aligned.m8n8.x4.shared.b16 {%0,%1,%2,%3}, [%4];"
                 : "=r"(r[0]), "=r"(r[1]), "=r"(r[2]), "=r"(r[3]) : "r"(addr));
}
__device__ __forceinline__ void mma16816(float* d, const uint32_t* a, const uint32_t* b) {
    asm volatile(
        "mma.sync.aligned.m16n8k16.row.col.f32.bf16.bf16.f32 "
        "{%0,%1,%2,%3}, {%4,%5,%6,%7}, {%8,%9}, {%0,%1,%2,%3};"
        : "+f"(d[0]), "+f"(d[1]), "+f"(d[2]), "+f"(d[3])
        : "r"(a[0]), "r"(a[1]), "r"(a[2]), "r"(a[3]), "r"(b[0]), "r"(b[1]));
}

// ---------------------------------------------------------------------------
// bf16 split GEMM via mma.sync:  C[bz] = act(A @ Bw^T + bias)
//   A: [M, 2K] bf16, Bw: [N, 2K] bf16, bias fp32 [N]
//   3 passes accumulate: Ah*Bh + Al*Bh + Ah*Bl
// CTA 128x128, BK=64, 4 stages, 256 threads (8 warps of 32x64).
// ---------------------------------------------------------------------------
#define TILE_M 128
#define TILE_N 128
#define BK 64
#define STAGES 4
#define A_BYTES (TILE_M * 128)
#define B_BYTES (TILE_N * 128)
#define STAGE_BYTES (A_BYTES + B_BYTES)
#define GEMM_SMEM (STAGES * STAGE_BYTES)

template <int ACT, int OUTF32>
__global__ void __launch_bounds__(256, 1) gemm_mma(
    const __nv_bfloat16* __restrict__ A, const __nv_bfloat16* __restrict__ Bw,
    const float* __restrict__ bias, void* __restrict__ Cout,
    int N, int Kd, size_t sA, size_t sB, size_t sBias, size_t sC)
{
    extern __shared__ __align__(1024) char smem[];
    const uint32_t sb = smem_u32(smem);
    const int tid = threadIdx.x, wid = tid >> 5, lane = tid & 31;
    const int bz = blockIdx.z;
    A    += (size_t)bz * sA;
    Bw   += (size_t)bz * sB;
    bias += (size_t)bz * sBias;

    const int bm = blockIdx.y * TILE_M;
    const int bn = blockIdx.x * TILE_N;
    const int ldA = 2 * Kd;
    const int npass = Kd / BK;            // chunks per pass
    const int total = 3 * npass;

    // ---- producer thread mapping (cp.async) ----
    const int prow = tid >> 3;            // 0..31
    const int pch  = tid & 7;             // 16B granule in 128B row
    const uint32_t pxor = (uint32_t)((prow & 7) << 4);
    const __nv_bfloat16* Ag = A  + (size_t)(bm + prow) * ldA + pch * 8;
    const __nv_bfloat16* Bg = Bw + (size_t)(bn + prow) * ldA + pch * 8;

    // ---- warp compute mapping ----
    const int m_off = (wid & 3) * 32;
    const int n_off = (wid >> 2) * 64;
    // A ldmatrix lanes
    const int ar = lane & 15, ah = lane >> 4;
    const uint32_t aXor = (uint32_t)((ar & 7) << 4);
    uint32_t aRow[2];
#pragma unroll
    for (int mi = 0; mi < 2; mi++)
        aRow[mi] = (uint32_t)((m_off + mi * 16 + ar) * 128);
    const uint32_t aKad = (uint32_t)(ah * 16);
    // B ldmatrix lanes
    const int l8 = lane & 7, sel = lane >> 3;
    const uint32_t bXor = (uint32_t)((l8 & 7) << 4);
    uint32_t bRow[4];
#pragma unroll
    for (int j = 0; j < 4; j++)
        bRow[j] = (uint32_t)((n_off + j * 16 + ((sel >> 1) * 8) + l8) * 128);
    const uint32_t bKad = (uint32_t)((sel & 1) * 16);

    float acc[2][8][4];
#pragma unroll
    for (int mi = 0; mi < 2; mi++)
#pragma unroll
        for (int nj = 0; nj < 8; nj++)
#pragma unroll
            for (int c = 0; c < 4; c++) acc[mi][nj][c] = 0.0f;

    auto load_chunk = [&](int c, int s) {
        const int pass = c / npass;
        const int k0 = (c - pass * npass) * BK;
        const int ka = (pass == 1 ? Kd : 0) + k0;
        const int kb = (pass == 2 ? Kd : 0) + k0;
        const uint32_t ab = sb + s * STAGE_BYTES;
        const uint32_t bb = ab + A_BYTES;
        const uint32_t doff = (uint32_t)(prow * 128) + (((uint32_t)(pch * 16)) ^ pxor);
#pragma unroll
        for (int i = 0; i < 4; i++)
            cpa16(ab + doff + (uint32_t)(i * 32 * 128), Ag + (size_t)(32 * i) * ldA + ka);
#pragma unroll
        for (int i = 0; i < 4; i++)
            cpa16(bb + doff + (uint32_t)(i * 32 * 128), Bg + (size_t)(32 * i) * ldA + kb);
    };

    // prologue
    for (int s = 0; s < STAGES - 1; s++) {
        load_chunk(s, s);
        CP_COMMIT();
    }

    for (int it = 0; it < total; it++) {
        CP_WAIT2();
        __syncthreads();
        const int nc = it + STAGES - 1;
        if (nc < total) load_chunk(nc, nc % STAGES);
        CP_COMMIT();

        const int s = it % STAGES;
        const uint32_t ab = sb + s * STAGE_BYTES;
        const uint32_t bb = ab + A_BYTES;
#pragma unroll
        for (int ks = 0; ks < BK / 16; ks++) {
            uint32_t af[2][4];
            uint32_t bfr[8][2];
#pragma unroll
            for (int mi = 0; mi < 2; mi++)
                ldm4(af[mi], ab + aRow[mi] + (((uint32_t)(ks * 32) + aKad) ^ aXor));
#pragma unroll
            for (int j = 0; j < 4; j++) {
                uint32_t r[4];
                ldm4(r, bb + bRow[j] + (((uint32_t)(ks * 32) + bKad) ^ bXor));
                bfr[2 * j][0] = r[0]; bfr[2 * j][1] = r[1];
                bfr[2 * j + 1][0] = r[2]; bfr[2 * j + 1][1] = r[3];
            }
#pragma unroll
            for (int mi = 0; mi < 2; mi++)
#pragma unroll
                for (int nj = 0; nj < 8; nj++)
                    mma16816(acc[mi][nj], af[mi], bfr[nj]);
        }
    }

    // ---- epilogue ----
    const int crow = lane >> 2;
    const int ccol = (lane & 3) * 2;
#pragma unroll
    for (int nj = 0; nj < 8; nj++) {
        const int col = bn + n_off + nj * 8 + ccol;
        const float2 bb2 = *(const float2*)(bias + col);
#pragma unroll
        for (int mi = 0; mi < 2; mi++) {
            const int r0 = bm + m_off + mi * 16 + crow;
#pragma unroll
            for (int h = 0; h < 2; h++) {            // top / bottom 8 rows
                const int row = r0 + 8 * h;
                float v0 = acc[mi][nj][2 * h + 0] + bb2.x;
                float v1 = acc[mi][nj][2 * h + 1] + bb2.y;
                if (ACT == 1) { v0 = tanhf(v0); v1 = tanhf(v1); }
                else if (ACT == 2) { v0 = fmaxf(v0, 0.f); v1 = fmaxf(v1, 0.f); }
                if (OUTF32) {
                    float* dst = (float*)Cout + (size_t)bz * sC + (size_t)row * N + col;
                    *(float2*)dst = make_float2(v0, v1);
                } else {
                    __nv_bfloat16 h0 = __float2bfloat16(v0);
                    __nv_bfloat16 h1 = __float2bfloat16(v1);
                    __nv_bfloat16 l0 = __float2bfloat16(v0 - __bfloat162float(h0));
                    __nv_bfloat16 l1 = __float2bfloat16(v1 - __bfloat162float(h1));
                    __nv_bfloat162 hh = __halves2bfloat162(h0, h1);
                    __nv_bfloat162 ll = __halves2bfloat162(l0, l1);
                    __nv_bfloat16* base = (__nv_bfloat16*)Cout + (size_t)bz * sC +
                                          (size_t)row * (2 * N) + col;
                    *(uint32_t*)base = *(uint32_t*)&hh;
                    *(uint32_t*)(base + N) = *(uint32_t*)&ll;
                }
            }
        }
    }
}

// ---------------------------------------------------------------------------
// Prep kernels
// ---------------------------------------------------------------------------
__global__ void xsplit(const float* __restrict__ x, __nv_bfloat16* __restrict__ T0) {
    size_t i = (size_t)blockIdx.x * 256 + threadIdx.x;
    float val = x[i];
    __nv_bfloat16 h = __float2bfloat16(val);
    __nv_bfloat16 l = __float2bfloat16(val - __bfloat162float(h));
    size_t b = i / Dn, d = i % Dn;
    T0[b * (2 * Dn) + d] = h;
    T0[b * (2 * Dn) + Dn + d] = l;
}

__global__ void wsplit(const float* __restrict__ W, __nv_bfloat16* __restrict__ WT,
                       int Kd, int N, size_t sW, size_t sWT) {
    __shared__ float t[32][33];
    const int bz = blockIdx.z;
    W  += (size_t)bz * sW;
    WT += (size_t)bz * sWT;
    const int n0 = blockIdx.x * 32, k0 = blockIdx.y * 32;
    const int tx = threadIdx.x, ty = threadIdx.y;
    for (int i = 0; i < 32; i += 8)
        t[ty + i][tx] = W[(size_t)(k0 + ty + i) * N + n0 + tx];
    __syncthreads();
    for (int i = 0; i < 32; i += 8) {
        float val = t[tx][ty + i];
        __nv_bfloat16 h = __float2bfloat16(val);
        __nv_bfloat16 l = __float2bfloat16(val - __bfloat162float(h));
        size_t rowo = (size_t)(n0 + ty + i) * (2 * Kd);
        WT[rowo + k0 + tx] = h;
        WT[rowo + Kd + k0 + tx] = l;
    }
}

// ---------------------------------------------------------------------------
// Gram + normalize + score (unchanged, proven in R1)
// ---------------------------------------------------------------------------
__device__ __forceinline__ void pair_of(int p, int& i, int& j) {
    int ii = 0, rem = p;
    while (rem >= NV - ii) { rem -= NV - ii; ii++; }
    i = ii; j = ii + rem;
}
#define CHUNK 256
#define MAXP_PER_WARP 10

__global__ void gram_score(const float* __restrict__ Z, float* __restrict__ out) {
    __shared__ float chunk[NV][CHUNK];
    __shared__ float sG[NV * NV];
    const int b = blockIdx.x, tid = threadIdx.x;
    const int lane = tid & 31, warp = tid >> 5;

    int pi_i[MAXP_PER_WARP], pi_j[MAXP_PER_WARP];
    float accp[MAXP_PER_WARP];
#pragma unroll
    for (int pi = 0; pi < MAXP_PER_WARP; pi++) {
        int p = warp + pi * 8;
        if (p < NPAIR) pair_of(p, pi_i[pi], pi_j[pi]);
        else { pi_i[pi] = 0; pi_j[pi] = 0; }
        accp[pi] = 0.0f;
    }
    for (int h0 = 0; h0 < Hn; h0 += CHUNK) {
        __syncthreads();
        for (int i = tid; i < NV * (CHUNK / 4); i += 256) {
            int v = i / (CHUNK / 4);
            int h4 = (i % (CHUNK / 4)) * 4;
            float4 val = *(const float4*)(Z + (size_t)v * Bn * Hn + (size_t)b * Hn + h0 + h4);
            *(float4*)(&chunk[v][h4]) = val;
        }
        __syncthreads();
#pragma unroll
        for (int pi = 0; pi < MAXP_PER_WARP; pi++) {
            int p = warp + pi * 8;
            if (p < NPAIR) {
                const float* ri = chunk[pi_i[pi]];
                const float* rj = chunk[pi_j[pi]];
                float s = 0.0f;
#pragma unroll
                for (int t = 0; t < CHUNK / 32; t++)
                    s = fmaf(ri[lane + 32 * t], rj[lane + 32 * t], s);
                accp[pi] += s;
            }
        }
    }
#pragma unroll
    for (int pi = 0; pi < MAXP_PER_WARP; pi++) {
        int p = warp + pi * 8;
        if (p < NPAIR) {
            float s = accp[pi];
#pragma unroll
            for (int o = 16; o; o >>= 1) s += __shfl_xor_sync(0xffffffffu, s, o);
            if (lane == 0) {
                sG[pi_i[pi] * NV + pi_j[pi]] = s;
                sG[pi_j[pi] * NV + pi_i[pi]] = s;
            }
        }
    }
    __syncthreads();
    if (tid == 0) {
        float nm[NV];
#pragma unroll
        for (int i = 0; i < NV; i++) nm[i] = fmaxf(sqrtf(sG[i * NV + i]), EPSF);
        float total = 0.0f;
        for (int k = 1; k < NV; k++) {
            float pos = expf(sG[k] / (nm[0] * nm[k]));
            float neg = 0.0f;
            for (int l = 1; l < NV; l++)
                if (l != k) neg += expf(sG[k * NV + l] / (nm[k] * nm[l]));
            total += logf((pos + neg) / pos);
        }
        out[b] = total;
    }
}

// ---------------------------------------------------------------------------
// Launch
// ---------------------------------------------------------------------------
extern "C" void kernel_launch(void* const* d_in, const int* in_sizes, int n_in,
                              void* d_out, int out_size)
{
    const float* x   = (const float*)d_in[0];
    const float* Wt1 = (const float*)d_in[1];
    const float* bt1 = (const float*)d_in[2];
    const float* Wt2 = (const float*)d_in[3];
    const float* bt2 = (const float*)d_in[4];
    const float* We1 = (const float*)d_in[5];
    const float* be1 = (const float*)d_in[6];
    const float* We2 = (const float*)d_in[7];
    const float* be2 = (const float*)d_in[8];
    float* out = (float*)d_out;

    __nv_bfloat16 *T, *H, *WT1, *WT2, *WE1, *WE2;
    float* Z;
    cudaGetSymbolAddress((void**)&T, g_T);
    cudaGetSymbolAddress((void**)&H, g_H);
    cudaGetSymbolAddress((void**)&Z, g_Z);
    cudaGetSymbolAddress((void**)&WT1, g_WT1);
    cudaGetSymbolAddress((void**)&WT2, g_WT2);
    cudaGetSymbolAddress((void**)&WE1, g_WE1);
    cudaGetSymbolAddress((void**)&WE2, g_WE2);

    xsplit<<<(Bn * Dn) / 256, 256>>>(x, T);
    wsplit<<<dim3(Hn / 32, Dn / 32, KV), dim3(32, 8)>>>(
        Wt1, WT1, Dn, Hn, (size_t)Dn * Hn, (size_t)Hn * 2 * Dn);
    wsplit<<<dim3(Dn / 32, Hn / 32, KV), dim3(32, 8)>>>(
        Wt2, WT2, Hn, Dn, (size_t)Hn * Dn, (size_t)Dn * 2 * Hn);
    wsplit<<<dim3(Hn / 32, Dn / 32, 1), dim3(32, 8)>>>(We1, WE1, Dn, Hn, 0, 0);
    wsplit<<<dim3(Hn / 32, Hn / 32, 1), dim3(32, 8)>>>(We2, WE2, Hn, Hn, 0, 0);

    cudaFuncSetAttribute(gemm_mma<1, 0>, cudaFuncAttributeMaxDynamicSharedMemorySize, GEMM_SMEM);
    cudaFuncSetAttribute(gemm_mma<0, 0>, cudaFuncAttributeMaxDynamicSharedMemorySize, GEMM_SMEM);
    cudaFuncSetAttribute(gemm_mma<2, 0>, cudaFuncAttributeMaxDynamicSharedMemorySize, GEMM_SMEM);
    cudaFuncSetAttribute(gemm_mma<0, 1>, cudaFuncAttributeMaxDynamicSharedMemorySize, GEMM_SMEM);

    // A1: H[k] = tanh(x @ Wt1[k] + bt1[k])
    gemm_mma<1, 0><<<dim3(Hn / TILE_N, Bn / TILE_M, KV), 256, GEMM_SMEM>>>(
        T, WT1, bt1, H, Hn, Dn,
        (size_t)0, (size_t)Hn * 2 * Dn, (size_t)Hn, (size_t)Bn * 2 * Hn);

    // A2: T[1+k] = H[k] @ Wt2[k] + bt2[k]
    gemm_mma<0, 0><<<dim3(Dn / TILE_N, Bn / TILE_M, KV), 256, GEMM_SMEM>>>(
        H, WT2, bt2, T + (size_t)Bn * 2 * Dn, Dn, Hn,
        (size_t)Bn * 2 * Hn, (size_t)Dn * 2 * Hn, (size_t)Dn, (size_t)Bn * 2 * Dn);

    // B1: H[v] = relu(T[v] @ We1 + be1)
    gemm_mma<2, 0><<<dim3(Hn / TILE_N, Bn / TILE_M, NV), 256, GEMM_SMEM>>>(
        T, WE1, be1, H, Hn, Dn,
        (size_t)Bn * 2 * Dn, (size_t)0, (size_t)0, (size_t)Bn * 2 * Hn);

    // B2: Z[v] = H[v] @ We2 + be2  (fp32 out)
    gemm_mma<0, 1><<<dim3(Hn / TILE_N, Bn / TILE_M, NV), 256, GEMM_SMEM>>>(
        H, WE2, be2, Z, Hn, Hn,
        (size_t)Bn * 2 * Hn, (size_t)0, (size_t)0, (size_t)Bn * Hn);

    gram_score<<<Bn, 256>>>(Z, out);
}

// round 4
// speedup vs baseline: 2.4340x; 1.0801x over previous
#include <cuda_runtime.h>
#include <cuda_bf16.h>
#include <cstddef>
#include <cstdint>

#define Bn 8192
#define Dn 512
#define Hn 1024
#define KV 11
#define NV 12
#define NPAIR 78
#define EPSF 1e-8f

// ---------------------------------------------------------------------------
// Device scratch.  Split-bf16 activations: [rows, 2*K] (hi | lo along K).
// Weights transposed+split: WT[n, 2*K].
// ---------------------------------------------------------------------------
__device__ __align__(1024) __nv_bfloat16 g_T[(size_t)NV * Bn * (2 * Dn)];
__device__ __align__(1024) __nv_bfloat16 g_H[(size_t)NV * Bn * (2 * Hn)];
__device__ __align__(1024) float        g_Z[(size_t)NV * Bn * Hn];
__device__ __align__(1024) __nv_bfloat16 g_WT1[(size_t)KV * Hn * (2 * Dn)];
__device__ __align__(1024) __nv_bfloat16 g_WT2[(size_t)KV * Dn * (2 * Hn)];
__device__ __align__(1024) __nv_bfloat16 g_WE1[(size_t)Hn * (2 * Dn)];
__device__ __align__(1024) __nv_bfloat16 g_WE2[(size_t)Hn * (2 * Hn)];

// ---------------------------------------------------------------------------
__device__ __forceinline__ uint32_t smem_u32(const void* p) {
    uint32_t a;
    asm("{ .reg .u64 t; cvta.to.shared.u64 t, %1; cvt.u32.u64 %0, t; }" : "=r"(a) : "l"(p));
    return a;
}
__device__ __forceinline__ void cpa16(uint32_t dst, const void* src) {
    asm volatile("cp.async.cg.shared.global [%0], [%1], 16;" :: "r"(dst), "l"(src) : "memory");
}
#define CP_COMMIT() asm volatile("cp.async.commit_group;" ::: "memory")
#define CP_WAIT2()  asm volatile("cp.async.wait_group 2;" ::: "memory")

__device__ __forceinline__ void ldm4(uint32_t* r, uint32_t addr) {
    asm volatile("ldmatrix.sync.aligned.m8n8.x4.shared.b16 {%0,%1,%2,%3}, [%4];"
                 : "=r"(r[0]), "=r"(r[1]), "=r"(r[2]), "=r"(r[3]) : "r"(addr));
}
__device__ __forceinline__ void mma16816(float* d, const uint32_t* a, const uint32_t* b) {
    asm volatile(
        "mma.sync.aligned.m16n8k16.row.col.f32.bf16.bf16.f32 "
        "{%0,%1,%2,%3}, {%4,%5,%6,%7}, {%8,%9}, {%0,%1,%2,%3};"
        : "+f"(d[0]), "+f"(d[1]), "+f"(d[2]), "+f"(d[3])
        : "r"(a[0]), "r"(a[1]), "r"(a[2]), "r"(a[3]), "r"(b[0]), "r"(b[1]));
}

// ---------------------------------------------------------------------------
// bf16 split GEMM via mma.sync:  C[bz] = act(A @ Bw^T + bias)
//   3 passes accumulate: Ah*Bh + Al*Bh + Ah*Bl
// CTA 128x256, BK=64, 4 stages, 512 threads (16 warps of 32x64).
// ---------------------------------------------------------------------------
#define TILE_M 128
#define TILE_N 256
#define BK 64
#define STAGES 4
#define A_BYTES (TILE_M * 128)
#define B_BYTES (TILE_N * 128)
#define STAGE_BYTES (A_BYTES + B_BYTES)
#define GEMM_SMEM (STAGES * STAGE_BYTES)

template <int ACT, int OUTF32>
__global__ void __launch_bounds__(512, 1) gemm_mma(
    const __nv_bfloat16* __restrict__ A, const __nv_bfloat16* __restrict__ Bw,
    const float* __restrict__ bias, void* __restrict__ Cout,
    int N, int Kd, size_t sA, size_t sB, size_t sBias, size_t sC)
{
    extern __shared__ __align__(1024) char smem[];
    const uint32_t sb = smem_u32(smem);
    const int tid = threadIdx.x, wid = tid >> 5, lane = tid & 31;
    const int bz = blockIdx.z;
    A    += (size_t)bz * sA;
    Bw   += (size_t)bz * sB;
    bias += (size_t)bz * sBias;

    const int bm = blockIdx.y * TILE_M;
    const int bn = blockIdx.x * TILE_N;
    const int ldA = 2 * Kd;
    const int npass = Kd / BK;
    const int total = 3 * npass;

    // ---- producer mapping: 512 threads, 64 rows x 8 granules ----
    const int prow = tid >> 3;            // 0..63
    const int pch  = tid & 7;             // 16B granule in 128B row
    const uint32_t doff = (uint32_t)(prow * 128) +
                          (((uint32_t)(pch * 16)) ^ (uint32_t)((prow & 7) << 4));
    const __nv_bfloat16* Ag = A  + (size_t)(bm + prow) * ldA + pch * 8;
    const __nv_bfloat16* Bg = Bw + (size_t)(bn + prow) * ldA + pch * 8;

    // ---- warp compute mapping: 4 m-warps x 4 n-warps ----
    const int m_off = (wid & 3) * 32;
    const int n_off = (wid >> 2) * 64;
    const int ar = lane & 15, ah = lane >> 4;
    const uint32_t aXor = (uint32_t)((ar & 7) << 4);
    uint32_t aRow[2];
#pragma unroll
    for (int mi = 0; mi < 2; mi++)
        aRow[mi] = (uint32_t)((m_off + mi * 16 + ar) * 128);
    const uint32_t aKad = (uint32_t)(ah * 16);
    const int l8 = lane & 7, sel = lane >> 3;
    const uint32_t bXor = (uint32_t)((l8 & 7) << 4);
    uint32_t bRow[4];
#pragma unroll
    for (int j = 0; j < 4; j++)
        bRow[j] = (uint32_t)((n_off + j * 16 + ((sel >> 1) * 8) + l8) * 128);
    const uint32_t bKad = (uint32_t)((sel & 1) * 16);

    float acc[2][8][4];
#pragma unroll
    for (int mi = 0; mi < 2; mi++)
#pragma unroll
        for (int nj = 0; nj < 8; nj++)
#pragma unroll
            for (int c = 0; c < 4; c++) acc[mi][nj][c] = 0.0f;

    auto load_chunk = [&](int c, int s) {
        const int pass = c / npass;
        const int k0 = (c - pass * npass) * BK;
        const int ka = (pass == 1 ? Kd : 0) + k0;
        const int kb = (pass == 2 ? Kd : 0) + k0;
        const uint32_t ab = sb + s * STAGE_BYTES;
        const uint32_t bb = ab + A_BYTES;
#pragma unroll
        for (int i = 0; i < 2; i++)
            cpa16(ab + doff + (uint32_t)(i * 64 * 128), Ag + (size_t)(64 * i) * ldA + ka);
#pragma unroll
        for (int i = 0; i < 4; i++)
            cpa16(bb + doff + (uint32_t)(i * 64 * 128), Bg + (size_t)(64 * i) * ldA + kb);
    };

    for (int s = 0; s < STAGES - 1; s++) {
        load_chunk(s, s);
        CP_COMMIT();
    }

    for (int it = 0; it < total; it++) {
        CP_WAIT2();
        __syncthreads();
        const int nc = it + STAGES - 1;
        if (nc < total) load_chunk(nc, nc % STAGES);
        CP_COMMIT();

        const int s = it % STAGES;
        const uint32_t ab = sb + s * STAGE_BYTES;
        const uint32_t bb = ab + A_BYTES;
#pragma unroll
        for (int ks = 0; ks < BK / 16; ks++) {
            uint32_t af[2][4];
            uint32_t bfr[8][2];
#pragma unroll
            for (int mi = 0; mi < 2; mi++)
                ldm4(af[mi], ab + aRow[mi] + (((uint32_t)(ks * 32) + aKad) ^ aXor));
#pragma unroll
            for (int j = 0; j < 4; j++) {
                uint32_t r[4];
                ldm4(r, bb + bRow[j] + (((uint32_t)(ks * 32) + bKad) ^ bXor));
                bfr[2 * j][0] = r[0]; bfr[2 * j][1] = r[1];
                bfr[2 * j + 1][0] = r[2]; bfr[2 * j + 1][1] = r[3];
            }
#pragma unroll
            for (int mi = 0; mi < 2; mi++)
#pragma unroll
                for (int nj = 0; nj < 8; nj++)
                    mma16816(acc[mi][nj], af[mi], bfr[nj]);
        }
    }

    // ---- epilogue ----
    const int crow = lane >> 2;
    const int ccol = (lane & 3) * 2;
#pragma unroll
    for (int nj = 0; nj < 8; nj++) {
        const int col = bn + n_off + nj * 8 + ccol;
        const float2 bb2 = *(const float2*)(bias + col);
#pragma unroll
        for (int mi = 0; mi < 2; mi++) {
            const int r0 = bm + m_off + mi * 16 + crow;
#pragma unroll
            for (int h = 0; h < 2; h++) {
                const int row = r0 + 8 * h;
                float v0 = acc[mi][nj][2 * h + 0] + bb2.x;
                float v1 = acc[mi][nj][2 * h + 1] + bb2.y;
                if (ACT == 1) { v0 = tanhf(v0); v1 = tanhf(v1); }
                else if (ACT == 2) { v0 = fmaxf(v0, 0.f); v1 = fmaxf(v1, 0.f); }
                if (OUTF32) {
                    float* dst = (float*)Cout + (size_t)bz * sC + (size_t)row * N + col;
                    *(float2*)dst = make_float2(v0, v1);
                } else {
                    __nv_bfloat16 h0 = __float2bfloat16(v0);
                    __nv_bfloat16 h1 = __float2bfloat16(v1);
                    __nv_bfloat16 l0 = __float2bfloat16(v0 - __bfloat162float(h0));
                    __nv_bfloat16 l1 = __float2bfloat16(v1 - __bfloat162float(h1));
                    __nv_bfloat162 hh = __halves2bfloat162(h0, h1);
                    __nv_bfloat162 ll = __halves2bfloat162(l0, l1);
                    __nv_bfloat16* base = (__nv_bfloat16*)Cout + (size_t)bz * sC +
                                          (size_t)row * (2 * N) + col;
                    *(uint32_t*)base = *(uint32_t*)&hh;
                    *(uint32_t*)(base + N) = *(uint32_t*)&ll;
                }
            }
        }
    }
}

// ---------------------------------------------------------------------------
// Prep kernels
// ---------------------------------------------------------------------------
__global__ void xsplit(const float* __restrict__ x, __nv_bfloat16* __restrict__ T0) {
    size_t i = (size_t)blockIdx.x * 256 + threadIdx.x;
    float val = x[i];
    __nv_bfloat16 h = __float2bfloat16(val);
    __nv_bfloat16 l = __float2bfloat16(val - __bfloat162float(h));
    size_t b = i / Dn, d = i % Dn;
    T0[b * (2 * Dn) + d] = h;
    T0[b * (2 * Dn) + Dn + d] = l;
}

__global__ void wsplit(const float* __restrict__ W, __nv_bfloat16* __restrict__ WT,
                       int Kd, int N, size_t sW, size_t sWT) {
    __shared__ float t[32][33];
    const int bz = blockIdx.z;
    W  += (size_t)bz * sW;
    WT += (size_t)bz * sWT;
    const int n0 = blockIdx.x * 32, k0 = blockIdx.y * 32;
    const int tx = threadIdx.x, ty = threadIdx.y;
    for (int i = 0; i < 32; i += 8)
        t[ty + i][tx] = W[(size_t)(k0 + ty + i) * N + n0 + tx];
    __syncthreads();
    for (int i = 0; i < 32; i += 8) {
        float val = t[tx][ty + i];
        __nv_bfloat16 h = __float2bfloat16(val);
        __nv_bfloat16 l = __float2bfloat16(val - __bfloat162float(h));
        size_t rowo = (size_t)(n0 + ty + i) * (2 * Kd);
        WT[rowo + k0 + tx] = h;
        WT[rowo + Kd + k0 + tx] = l;
    }
}

// ---------------------------------------------------------------------------
// Gram + normalize + score
// ---------------------------------------------------------------------------
__device__ __forceinline__ void pair_of(int p, int& i, int& j) {
    int ii = 0, rem = p;
    while (rem >= NV - ii) { rem -= NV - ii; ii++; }
    i = ii; j = ii + rem;
}
#define CHUNK 256
#define MAXP_PER_WARP 10

__global__ void gram_score(const float* __restrict__ Z, float* __restrict__ out) {
    __shared__ float chunk[NV][CHUNK];
    __shared__ float sG[NV * NV];
    const int b = blockIdx.x, tid = threadIdx.x;
    const int lane = tid & 31, warp = tid >> 5;

    int pi_i[MAXP_PER_WARP], pi_j[MAXP_PER_WARP];
    float accp[MAXP_PER_WARP];
#pragma unroll
    for (int pi = 0; pi < MAXP_PER_WARP; pi++) {
        int p = warp + pi * 8;
        if (p < NPAIR) pair_of(p, pi_i[pi], pi_j[pi]);
        else { pi_i[pi] = 0; pi_j[pi] = 0; }
        accp[pi] = 0.0f;
    }
    for (int h0 = 0; h0 < Hn; h0 += CHUNK) {
        __syncthreads();
        for (int i = tid; i < NV * (CHUNK / 4); i += 256) {
            int v = i / (CHUNK / 4);
            int h4 = (i % (CHUNK / 4)) * 4;
            float4 val = *(const float4*)(Z + (size_t)v * Bn * Hn + (size_t)b * Hn + h0 + h4);
            *(float4*)(&chunk[v][h4]) = val;
        }
        __syncthreads();
#pragma unroll
        for (int pi = 0; pi < MAXP_PER_WARP; pi++) {
            int p = warp + pi * 8;
            if (p < NPAIR) {
                const float* ri = chunk[pi_i[pi]];
                const float* rj = chunk[pi_j[pi]];
                float s = 0.0f;
#pragma unroll
                for (int t = 0; t < CHUNK / 32; t++)
                    s = fmaf(ri[lane + 32 * t], rj[lane + 32 * t], s);
                accp[pi] += s;
            }
        }
    }
#pragma unroll
    for (int pi = 0; pi < MAXP_PER_WARP; pi++) {
        int p = warp + pi * 8;
        if (p < NPAIR) {
            float s = accp[pi];
#pragma unroll
            for (int o = 16; o; o >>= 1) s += __shfl_xor_sync(0xffffffffu, s, o);
            if (lane == 0) {
                sG[pi_i[pi] * NV + pi_j[pi]] = s;
                sG[pi_j[pi] * NV + pi_i[pi]] = s;
            }
        }
    }
    __syncthreads();
    if (tid == 0) {
        float nm[NV];
#pragma unroll
        for (int i = 0; i < NV; i++) nm[i] = fmaxf(sqrtf(sG[i * NV + i]), EPSF);
        float total = 0.0f;
        for (int k = 1; k < NV; k++) {
            float pos = expf(sG[k] / (nm[0] * nm[k]));
            float neg = 0.0f;
            for (int l = 1; l < NV; l++)
                if (l != k) neg += expf(sG[k * NV + l] / (nm[k] * nm[l]));
            total += logf((pos + neg) / pos);
        }
        out[b] = total;
    }
}

// ---------------------------------------------------------------------------
// Launch
// ---------------------------------------------------------------------------
extern "C" void kernel_launch(void* const* d_in, const int* in_sizes, int n_in,
                              void* d_out, int out_size)
{
    const float* x   = (const float*)d_in[0];
    const float* Wt1 = (const float*)d_in[1];
    const float* bt1 = (const float*)d_in[2];
    const float* Wt2 = (const float*)d_in[3];
    const float* bt2 = (const float*)d_in[4];
    const float* We1 = (const float*)d_in[5];
    const float* be1 = (const float*)d_in[6];
    const float* We2 = (const float*)d_in[7];
    const float* be2 = (const float*)d_in[8];
    float* out = (float*)d_out;

    __nv_bfloat16 *T, *H, *WT1, *WT2, *WE1, *WE2;
    float* Z;
    cudaGetSymbolAddress((void**)&T, g_T);
    cudaGetSymbolAddress((void**)&H, g_H);
    cudaGetSymbolAddress((void**)&Z, g_Z);
    cudaGetSymbolAddress((void**)&WT1, g_WT1);
    cudaGetSymbolAddress((void**)&WT2, g_WT2);
    cudaGetSymbolAddress((void**)&WE1, g_WE1);
    cudaGetSymbolAddress((void**)&WE2, g_WE2);

    xsplit<<<(Bn * Dn) / 256, 256>>>(x, T);
    wsplit<<<dim3(Hn / 32, Dn / 32, KV), dim3(32, 8)>>>(
        Wt1, WT1, Dn, Hn, (size_t)Dn * Hn, (size_t)Hn * 2 * Dn);
    wsplit<<<dim3(Dn / 32, Hn / 32, KV), dim3(32, 8)>>>(
        Wt2, WT2, Hn, Dn, (size_t)Hn * Dn, (size_t)Dn * 2 * Hn);
    wsplit<<<dim3(Hn / 32, Dn / 32, 1), dim3(32, 8)>>>(We1, WE1, Dn, Hn, 0, 0);
    wsplit<<<dim3(Hn / 32, Hn / 32, 1), dim3(32, 8)>>>(We2, WE2, Hn, Hn, 0, 0);

    cudaFuncSetAttribute(gemm_mma<1, 0>, cudaFuncAttributeMaxDynamicSharedMemorySize, GEMM_SMEM);
    cudaFuncSetAttribute(gemm_mma<0, 0>, cudaFuncAttributeMaxDynamicSharedMemorySize, GEMM_SMEM);
    cudaFuncSetAttribute(gemm_mma<2, 0>, cudaFuncAttributeMaxDynamicSharedMemorySize, GEMM_SMEM);
    cudaFuncSetAttribute(gemm_mma<0, 1>, cudaFuncAttributeMaxDynamicSharedMemorySize, GEMM_SMEM);

    // A1: H[k] = tanh(x @ Wt1[k] + bt1[k])
    gemm_mma<1, 0><<<dim3(Hn / TILE_N, Bn / TILE_M, KV), 512, GEMM_SMEM>>>(
        T, WT1, bt1, H, Hn, Dn,
        (size_t)0, (size_t)Hn * 2 * Dn, (size_t)Hn, (size_t)Bn * 2 * Hn);

    // A2: T[1+k] = H[k] @ Wt2[k] + bt2[k]
    gemm_mma<0, 0><<<dim3(Dn / TILE_N, Bn / TILE_M, KV), 512, GEMM_SMEM>>>(
        H, WT2, bt2, T + (size_t)Bn * 2 * Dn, Dn, Hn,
        (size_t)Bn * 2 * Hn, (size_t)Dn * 2 * Hn, (size_t)Dn, (size_t)Bn * 2 * Dn);

    // B1: H[v] = relu(T[v] @ We1 + be1)
    gemm_mma<2, 0><<<dim3(Hn / TILE_N, Bn / TILE_M, NV), 512, GEMM_SMEM>>>(
        T, WE1, be1, H, Hn, Dn,
        (size_t)Bn * 2 * Dn, (size_t)0, (size_t)0, (size_t)Bn * 2 * Hn);

    // B2: Z[v] = H[v] @ We2 + be2  (fp32 out)
    gemm_mma<0, 1><<<dim3(Hn / TILE_N, Bn / TILE_M, NV), 512, GEMM_SMEM>>>(
        H, WE2, be2, Z, Hn, Hn,
        (size_t)Bn * 2 * Hn, (size_t)0, (size_t)0, (size_t)Bn * Hn);

    gram_score<<<Bn, 256>>>(Z, out);
}

// round 5
// speedup vs baseline: 3.5732x; 1.4680x over previous
#include <cuda_runtime.h>
#include <cuda_fp16.h>
#include <cstddef>
#include <cstdint>

#define Bn 8192
#define Dn 512
#define Hn 1024
#define KV 11
#define NV 12
#define NPAIR 78
#define EPSF 1e-8f

// ---------------------------------------------------------------------------
// Scratch. Activations split fp16: [rows, 2*K] (hi | lo along K).
// Weights transposed, fp16 hi only: WT[n, K].
// ---------------------------------------------------------------------------
__device__ __align__(1024) __half g_T[(size_t)NV * Bn * (2 * Dn)];
__device__ __align__(1024) __half g_H[(size_t)NV * Bn * (2 * Hn)];
__device__ __align__(1024) float  g_Z[(size_t)NV * Bn * Hn];
__device__ __align__(1024) __half g_WT1[(size_t)KV * Hn * Dn];
__device__ __align__(1024) __half g_WT2[(size_t)KV * Dn * Hn];
__device__ __align__(1024) __half g_WE1[(size_t)Hn * Dn];
__device__ __align__(1024) __half g_WE2[(size_t)Hn * Hn];

// ---------------------------------------------------------------------------
__device__ __forceinline__ uint32_t smem_u32(const void* p) {
    uint32_t a;
    asm("{ .reg .u64 t; cvta.to.shared.u64 t, %1; cvt.u32.u64 %0, t; }" : "=r"(a) : "l"(p));
    return a;
}
__device__ __forceinline__ void cpa16(uint32_t dst, const void* src) {
    asm volatile("cp.async.cg.shared.global [%0], [%1], 16;" :: "r"(dst), "l"(src) : "memory");
}
#define CP_COMMIT() asm volatile("cp.async.commit_group;" ::: "memory")
#define CP_WAIT1()  asm volatile("cp.async.wait_group 1;" ::: "memory")

__device__ __forceinline__ void ldm4(uint32_t* r, uint32_t addr) {
    asm volatile("ldmatrix.sync.aligned.m8n8.x4.shared.b16 {%0,%1,%2,%3}, [%4];"
                 : "=r"(r[0]), "=r"(r[1]), "=r"(r[2]), "=r"(r[3]) : "r"(addr));
}
__device__ __forceinline__ void mma16816(float* d, const uint32_t* a, const uint32_t* b) {
    asm volatile(
        "mma.sync.aligned.m16n8k16.row.col.f32.f16.f16.f32 "
        "{%0,%1,%2,%3}, {%4,%5,%6,%7}, {%8,%9}, {%0,%1,%2,%3};"
        : "+f"(d[0]), "+f"(d[1]), "+f"(d[2]), "+f"(d[3])
        : "r"(a[0]), "r"(a[1]), "r"(a[2]), "r"(a[3]), "r"(b[0]), "r"(b[1]));
}

// ---------------------------------------------------------------------------
// fp16 2-pass split GEMM:  C = act(A @ Bw^T + bias),  A=[M,2K] (hi|lo), Bw=[N,K]
//   acc = Ah*Bh + Al*Bh   (B ldmatrix shared by both passes)
// CTA 128x256, K-chunk 64, 3 stages (Ah 16K | Al 16K | B 32K = 64KB/stage).
// 512 threads = 16 warps of 32x64.
// ---------------------------------------------------------------------------
#define TILE_M 128
#define TILE_N 256
#define BK 64
#define STAGES 3
#define AH_BYTES (TILE_M * 128)
#define STAGE_BYTES (2 * AH_BYTES + TILE_N * 128)
#define GEMM_SMEM (STAGES * STAGE_BYTES)

template <int ACT, int OUTF32>
__global__ void __launch_bounds__(512, 1) gemm_mma(
    const __half* __restrict__ A, const __half* __restrict__ Bw,
    const float* __restrict__ bias, void* __restrict__ Cout,
    int N, int Kd, size_t sA, size_t sB, size_t sBias, size_t sC)
{
    extern __shared__ __align__(1024) char smem[];
    const uint32_t sb = smem_u32(smem);
    const int tid = threadIdx.x, wid = tid >> 5, lane = tid & 31;
    const int bz = blockIdx.z;
    A    += (size_t)bz * sA;
    Bw   += (size_t)bz * sB;
    bias += (size_t)bz * sBias;

    const int bm = blockIdx.y * TILE_M;
    const int bn = blockIdx.x * TILE_N;
    const int ldA = 2 * Kd;
    const int total = Kd / BK;

    // ---- producer mapping ----
    const int prow = tid >> 3;            // 0..63
    const int pch  = tid & 7;             // 16B granule in 128B row
    const uint32_t doff = (uint32_t)(prow * 128) +
                          (((uint32_t)(pch * 16)) ^ (uint32_t)((prow & 7) << 4));
    const __half* Ag = A  + (size_t)(bm + prow) * ldA + pch * 8;
    const __half* Bg = Bw + (size_t)(bn + prow) * Kd + pch * 8;

    // ---- warp compute mapping: 4 m-warps x 4 n-warps ----
    const int m_off = (wid & 3) * 32;
    const int n_off = (wid >> 2) * 64;
    const int ar = lane & 15, ah = lane >> 4;
    const uint32_t aXor = (uint32_t)((ar & 7) << 4);
    uint32_t aRow[2];
#pragma unroll
    for (int mi = 0; mi < 2; mi++)
        aRow[mi] = (uint32_t)((m_off + mi * 16 + ar) * 128);
    const uint32_t aKad = (uint32_t)(ah * 16);
    const int l8 = lane & 7, sel = lane >> 3;
    const uint32_t bXor = (uint32_t)((l8 & 7) << 4);
    uint32_t bRow[4];
#pragma unroll
    for (int j = 0; j < 4; j++)
        bRow[j] = (uint32_t)((n_off + j * 16 + ((sel >> 1) * 8) + l8) * 128);
    const uint32_t bKad = (uint32_t)((sel & 1) * 16);

    float acc[2][8][4];
#pragma unroll
    for (int mi = 0; mi < 2; mi++)
#pragma unroll
        for (int nj = 0; nj < 8; nj++)
#pragma unroll
            for (int c = 0; c < 4; c++) acc[mi][nj][c] = 0.0f;

    auto load_chunk = [&](int c, int s) {
        const int k0 = c * BK;
        const uint32_t hb = sb + s * STAGE_BYTES;          // Ah
        const uint32_t lb = hb + AH_BYTES;                 // Al
        const uint32_t bb = hb + 2 * AH_BYTES;             // B
#pragma unroll
        for (int i = 0; i < 2; i++) {
            cpa16(hb + doff + (uint32_t)(i * 8192), Ag + (size_t)(64 * i) * ldA + k0);
            cpa16(lb + doff + (uint32_t)(i * 8192), Ag + (size_t)(64 * i) * ldA + Kd + k0);
        }
#pragma unroll
        for (int i = 0; i < 4; i++)
            cpa16(bb + doff + (uint32_t)(i * 8192), Bg + (size_t)(64 * i) * Kd + k0);
    };

    for (int s = 0; s < STAGES - 1; s++) {
        load_chunk(s, s);
        CP_COMMIT();
    }

    for (int it = 0; it < total; it++) {
        CP_WAIT1();
        __syncthreads();
        const int nc = it + STAGES - 1;
        if (nc < total) load_chunk(nc, nc % STAGES);
        CP_COMMIT();

        const int s = it % STAGES;
        const uint32_t hb = sb + s * STAGE_BYTES;
        const uint32_t lb = hb + AH_BYTES;
        const uint32_t bb = hb + 2 * AH_BYTES;
#pragma unroll
        for (int ks = 0; ks < BK / 16; ks++) {
            uint32_t bfr[8][2];
#pragma unroll
            for (int j = 0; j < 4; j++) {
                uint32_t r[4];
                ldm4(r, bb + bRow[j] + (((uint32_t)(ks * 32) + bKad) ^ bXor));
                bfr[2 * j][0] = r[0]; bfr[2 * j][1] = r[1];
                bfr[2 * j + 1][0] = r[2]; bfr[2 * j + 1][1] = r[3];
            }
            uint32_t af[2][4];
            // pass hi
#pragma unroll
            for (int mi = 0; mi < 2; mi++)
                ldm4(af[mi], hb + aRow[mi] + (((uint32_t)(ks * 32) + aKad) ^ aXor));
#pragma unroll
            for (int mi = 0; mi < 2; mi++)
#pragma unroll
                for (int nj = 0; nj < 8; nj++)
                    mma16816(acc[mi][nj], af[mi], bfr[nj]);
            // pass lo
#pragma unroll
            for (int mi = 0; mi < 2; mi++)
                ldm4(af[mi], lb + aRow[mi] + (((uint32_t)(ks * 32) + aKad) ^ aXor));
#pragma unroll
            for (int mi = 0; mi < 2; mi++)
#pragma unroll
                for (int nj = 0; nj < 8; nj++)
                    mma16816(acc[mi][nj], af[mi], bfr[nj]);
        }
    }

    // ---- epilogue ----
    const int crow = lane >> 2;
    const int ccol = (lane & 3) * 2;
#pragma unroll
    for (int nj = 0; nj < 8; nj++) {
        const int col = bn + n_off + nj * 8 + ccol;
        const float2 bb2 = *(const float2*)(bias + col);
#pragma unroll
        for (int mi = 0; mi < 2; mi++) {
            const int r0 = bm + m_off + mi * 16 + crow;
#pragma unroll
            for (int h = 0; h < 2; h++) {
                const int row = r0 + 8 * h;
                float v0 = acc[mi][nj][2 * h + 0] + bb2.x;
                float v1 = acc[mi][nj][2 * h + 1] + bb2.y;
                if (ACT == 1) { v0 = tanhf(v0); v1 = tanhf(v1); }
                else if (ACT == 2) { v0 = fmaxf(v0, 0.f); v1 = fmaxf(v1, 0.f); }
                if (OUTF32) {
                    float* dst = (float*)Cout + (size_t)bz * sC + (size_t)row * N + col;
                    *(float2*)dst = make_float2(v0, v1);
                } else {
                    __half h0 = __float2half_rn(v0);
                    __half h1 = __float2half_rn(v1);
                    __half l0 = __float2half_rn(v0 - __half2float(h0));
                    __half l1 = __float2half_rn(v1 - __half2float(h1));
                    __half2 hh = __halves2half2(h0, h1);
                    __half2 ll = __halves2half2(l0, l1);
                    __half* base = (__half*)Cout + (size_t)bz * sC +
                                   (size_t)row * (2 * N) + col;
                    *(uint32_t*)base = *(uint32_t*)&hh;
                    *(uint32_t*)(base + N) = *(uint32_t*)&ll;
                }
            }
        }
    }
}

// ---------------------------------------------------------------------------
// Prep kernels
// ---------------------------------------------------------------------------
__global__ void xsplit(const float* __restrict__ x, __half* __restrict__ T0) {
    size_t i = (size_t)blockIdx.x * 256 + threadIdx.x;
    float val = x[i];
    __half h = __float2half_rn(val);
    __half l = __float2half_rn(val - __half2float(h));
    size_t b = i / Dn, d = i % Dn;
    T0[b * (2 * Dn) + d] = h;
    T0[b * (2 * Dn) + Dn + d] = l;
}

// W [K,N] fp32 -> WT [N,K] fp16 (transpose, round-to-nearest)
__global__ void wsplit(const float* __restrict__ W, __half* __restrict__ WT,
                       int Kd, int N, size_t sW, size_t sWT) {
    __shared__ float t[32][33];
    const int bz = blockIdx.z;
    W  += (size_t)bz * sW;
    WT += (size_t)bz * sWT;
    const int n0 = blockIdx.x * 32, k0 = blockIdx.y * 32;
    const int tx = threadIdx.x, ty = threadIdx.y;
    for (int i = 0; i < 32; i += 8)
        t[ty + i][tx] = W[(size_t)(k0 + ty + i) * N + n0 + tx];
    __syncthreads();
    for (int i = 0; i < 32; i += 8) {
        float val = t[tx][ty + i];
        WT[(size_t)(n0 + ty + i) * Kd + k0 + tx] = __float2half_rn(val);
    }
}

// ---------------------------------------------------------------------------
// Gram + normalize + score
// ---------------------------------------------------------------------------
__device__ __forceinline__ void pair_of(int p, int& i, int& j) {
    int ii = 0, rem = p;
    while (rem >= NV - ii) { rem -= NV - ii; ii++; }
    i = ii; j = ii + rem;
}
#define CHUNK 256
#define MAXP_PER_WARP 10

__global__ void gram_score(const float* __restrict__ Z, float* __restrict__ out) {
    __shared__ float chunk[NV][CHUNK];
    __shared__ float sG[NV * NV];
    const int b = blockIdx.x, tid = threadIdx.x;
    const int lane = tid & 31, warp = tid >> 5;

    int pi_i[MAXP_PER_WARP], pi_j[MAXP_PER_WARP];
    float accp[MAXP_PER_WARP];
#pragma unroll
    for (int pi = 0; pi < MAXP_PER_WARP; pi++) {
        int p = warp + pi * 8;
        if (p < NPAIR) pair_of(p, pi_i[pi], pi_j[pi]);
        else { pi_i[pi] = 0; pi_j[pi] = 0; }
        accp[pi] = 0.0f;
    }
    for (int h0 = 0; h0 < Hn; h0 += CHUNK) {
        __syncthreads();
        for (int i = tid; i < NV * (CHUNK / 4); i += 256) {
            int v = i / (CHUNK / 4);
            int h4 = (i % (CHUNK / 4)) * 4;
            float4 val = *(const float4*)(Z + (size_t)v * Bn * Hn + (size_t)b * Hn + h0 + h4);
            *(float4*)(&chunk[v][h4]) = val;
        }
        __syncthreads();
#pragma unroll
        for (int pi = 0; pi < MAXP_PER_WARP; pi++) {
            int p = warp + pi * 8;
            if (p < NPAIR) {
                const float* ri = chunk[pi_i[pi]];
                const float* rj = chunk[pi_j[pi]];
                float s = 0.0f;
#pragma unroll
                for (int t = 0; t < CHUNK / 32; t++)
                    s = fmaf(ri[lane + 32 * t], rj[lane + 32 * t], s);
                accp[pi] += s;
            }
        }
    }
#pragma unroll
    for (int pi = 0; pi < MAXP_PER_WARP; pi++) {
        int p = warp + pi * 8;
        if (p < NPAIR) {
            float s = accp[pi];
#pragma unroll
            for (int o = 16; o; o >>= 1) s += __shfl_xor_sync(0xffffffffu, s, o);
            if (lane == 0) {
                sG[pi_i[pi] * NV + pi_j[pi]] = s;
                sG[pi_j[pi] * NV + pi_i[pi]] = s;
            }
        }
    }
    __syncthreads();
    if (tid == 0) {
        float nm[NV];
#pragma unroll
        for (int i = 0; i < NV; i++) nm[i] = fmaxf(sqrtf(sG[i * NV + i]), EPSF);
        float total = 0.0f;
        for (int k = 1; k < NV; k++) {
            float pos = expf(sG[k] / (nm[0] * nm[k]));
            float neg = 0.0f;
            for (int l = 1; l < NV; l++)
                if (l != k) neg += expf(sG[k * NV + l] / (nm[k] * nm[l]));
            total += logf((pos + neg) / pos);
        }
        out[b] = total;
    }
}

// ---------------------------------------------------------------------------
// Launch
// ---------------------------------------------------------------------------
extern "C" void kernel_launch(void* const* d_in, const int* in_sizes, int n_in,
                              void* d_out, int out_size)
{
    const float* x   = (const float*)d_in[0];
    const float* Wt1 = (const float*)d_in[1];
    const float* bt1 = (const float*)d_in[2];
    const float* Wt2 = (const float*)d_in[3];
    const float* bt2 = (const float*)d_in[4];
    const float* We1 = (const float*)d_in[5];
    const float* be1 = (const float*)d_in[6];
    const float* We2 = (const float*)d_in[7];
    const float* be2 = (const float*)d_in[8];
    float* out = (float*)d_out;

    __half *T, *H, *WT1, *WT2, *WE1, *WE2;
    float* Z;
    cudaGetSymbolAddress((void**)&T, g_T);
    cudaGetSymbolAddress((void**)&H, g_H);
    cudaGetSymbolAddress((void**)&Z, g_Z);
    cudaGetSymbolAddress((void**)&WT1, g_WT1);
    cudaGetSymbolAddress((void**)&WT2, g_WT2);
    cudaGetSymbolAddress((void**)&WE1, g_WE1);
    cudaGetSymbolAddress((void**)&WE2, g_WE2);

    xsplit<<<(Bn * Dn) / 256, 256>>>(x, T);
    wsplit<<<dim3(Hn / 32, Dn / 32, KV), dim3(32, 8)>>>(
        Wt1, WT1, Dn, Hn, (size_t)Dn * Hn, (size_t)Hn * Dn);
    wsplit<<<dim3(Dn / 32, Hn / 32, KV), dim3(32, 8)>>>(
        Wt2, WT2, Hn, Dn, (size_t)Hn * Dn, (size_t)Dn * Hn);
    wsplit<<<dim3(Hn / 32, Dn / 32, 1), dim3(32, 8)>>>(We1, WE1, Dn, Hn, 0, 0);
    wsplit<<<dim3(Hn / 32, Hn / 32, 1), dim3(32, 8)>>>(We2, WE2, Hn, Hn, 0, 0);

    cudaFuncSetAttribute(gemm_mma<1, 0>, cudaFuncAttributeMaxDynamicSharedMemorySize, GEMM_SMEM);
    cudaFuncSetAttribute(gemm_mma<0, 0>, cudaFuncAttributeMaxDynamicSharedMemorySize, GEMM_SMEM);
    cudaFuncSetAttribute(gemm_mma<2, 0>, cudaFuncAttributeMaxDynamicSharedMemorySize, GEMM_SMEM);
    cudaFuncSetAttribute(gemm_mma<0, 1>, cudaFuncAttributeMaxDynamicSharedMemorySize, GEMM_SMEM);

    // A1: H[k] = tanh(x @ Wt1[k] + bt1[k])
    gemm_mma<1, 0><<<dim3(Hn / TILE_N, Bn / TILE_M, KV), 512, GEMM_SMEM>>>(
        T, WT1, bt1, H, Hn, Dn,
        (size_t)0, (size_t)Hn * Dn, (size_t)Hn, (size_t)Bn * 2 * Hn);

    // A2: T[1+k] = H[k] @ Wt2[k] + bt2[k]
    gemm_mma<0, 0><<<dim3(Dn / TILE_N, Bn / TILE_M, KV), 512, GEMM_SMEM>>>(
        H, WT2, bt2, T + (size_t)Bn * 2 * Dn, Dn, Hn,
        (size_t)Bn * 2 * Hn, (size_t)Dn * Hn, (size_t)Dn, (size_t)Bn * 2 * Dn);

    // B1: H[v] = relu(T[v] @ We1 + be1)
    gemm_mma<2, 0><<<dim3(Hn / TILE_N, Bn / TILE_M, NV), 512, GEMM_SMEM>>>(
        T, WE1, be1, H, Hn, Dn,
        (size_t)Bn * 2 * Dn, (size_t)0, (size_t)0, (size_t)Bn * 2 * Hn);

    // B2: Z[v] = H[v] @ We2 + be2  (fp32 out)
    gemm_mma<0, 1><<<dim3(Hn / TILE_N, Bn / TILE_M, NV), 512, GEMM_SMEM>>>(
        H, WE2, be2, Z, Hn, Hn,
        (size_t)Bn * 2 * Hn, (size_t)0, (size_t)0, (size_t)Bn * Hn);

    gram_score<<<Bn, 256>>>(Z, out);
}

// round 6
// speedup vs baseline: 5.8879x; 1.6478x over previous
#include <cuda_runtime.h>
#include <cuda_fp16.h>
#include <cstddef>
#include <cstdint>

#define Bn 8192
#define Dn 512
#define Hn 1024
#define KV 11
#define NV 12
#define NPAIR 78
#define EPSF 1e-8f

// ---------------------------------------------------------------------------
// Scratch: plain fp16 activations [rows, K]; weights transposed fp16 WT[n, K].
// ---------------------------------------------------------------------------
__device__ __align__(1024) __half g_T[(size_t)NV * Bn * Dn];
__device__ __align__(1024) __half g_H[(size_t)NV * Bn * Hn];
__device__ __align__(1024) float  g_Z[(size_t)NV * Bn * Hn];
__device__ __align__(1024) __half g_WT1[(size_t)KV * Hn * Dn];
__device__ __align__(1024) __half g_WT2[(size_t)KV * Dn * Hn];
__device__ __align__(1024) __half g_WE1[(size_t)Hn * Dn];
__device__ __align__(1024) __half g_WE2[(size_t)Hn * Hn];

// ---------------------------------------------------------------------------
__device__ __forceinline__ uint32_t smem_u32(const void* p) {
    uint32_t a;
    asm("{ .reg .u64 t; cvta.to.shared.u64 t, %1; cvt.u32.u64 %0, t; }" : "=r"(a) : "l"(p));
    return a;
}
__device__ __forceinline__ void cpa16(uint32_t dst, const void* src) {
    asm volatile("cp.async.cg.shared.global [%0], [%1], 16;" :: "r"(dst), "l"(src) : "memory");
}
#define CP_COMMIT() asm volatile("cp.async.commit_group;" ::: "memory")
#define CP_WAIT2()  asm volatile("cp.async.wait_group 2;" ::: "memory")

__device__ __forceinline__ void ldm4(uint32_t* r, uint32_t addr) {
    asm volatile("ldmatrix.sync.aligned.m8n8.x4.shared.b16 {%0,%1,%2,%3}, [%4];"
                 : "=r"(r[0]), "=r"(r[1]), "=r"(r[2]), "=r"(r[3]) : "r"(addr));
}
__device__ __forceinline__ void mma16816(float* d, const uint32_t* a, const uint32_t* b) {
    asm volatile(
        "mma.sync.aligned.m16n8k16.row.col.f32.f16.f16.f32 "
        "{%0,%1,%2,%3}, {%4,%5,%6,%7}, {%8,%9}, {%0,%1,%2,%3};"
        : "+f"(d[0]), "+f"(d[1]), "+f"(d[2]), "+f"(d[3])
        : "r"(a[0]), "r"(a[1]), "r"(a[2]), "r"(a[3]), "r"(b[0]), "r"(b[1]));
}

// ---------------------------------------------------------------------------
// fp16 GEMM (fp32 accum):  C = act(A @ Bw^T + bias),  A=[M,K], Bw=[N,K]
// CTA 128x256, K-chunk 64, 4 stages (A 16K | B 32K = 48KB/stage), 512 thr.
// ---------------------------------------------------------------------------
#define TILE_M 128
#define TILE_N 256
#define BK 64
#define STAGES 4
#define A_BYTES (TILE_M * 128)
#define STAGE_BYTES (A_BYTES + TILE_N * 128)
#define GEMM_SMEM (STAGES * STAGE_BYTES)

template <int ACT, int OUTF32>
__global__ void __launch_bounds__(512, 1) gemm_mma(
    const __half* __restrict__ A, const __half* __restrict__ Bw,
    const float* __restrict__ bias, void* __restrict__ Cout,
    int N, int Kd, size_t sA, size_t sB, size_t sBias, size_t sC)
{
    extern __shared__ __align__(1024) char smem[];
    const uint32_t sb = smem_u32(smem);
    const int tid = threadIdx.x, wid = tid >> 5, lane = tid & 31;
    const int bz = blockIdx.z;
    A    += (size_t)bz * sA;
    Bw   += (size_t)bz * sB;
    bias += (size_t)bz * sBias;

    const int bm = blockIdx.y * TILE_M;
    const int bn = blockIdx.x * TILE_N;
    const int total = Kd / BK;

    // ---- producer mapping: rows x 16B granules ----
    const int prow = tid >> 3;            // 0..63
    const int pch  = tid & 7;
    const uint32_t doff = (uint32_t)(prow * 128) +
                          (((uint32_t)(pch * 16)) ^ (uint32_t)((prow & 7) << 4));
    const __half* Ag = A  + (size_t)(bm + prow) * Kd + pch * 8;
    const __half* Bg = Bw + (size_t)(bn + prow) * Kd + pch * 8;

    // ---- warp compute mapping: 4 m-warps x 4 n-warps (32x64 each) ----
    const int m_off = (wid & 3) * 32;
    const int n_off = (wid >> 2) * 64;
    const int ar = lane & 15, ah = lane >> 4;
    const uint32_t aXor = (uint32_t)((ar & 7) << 4);
    uint32_t aRow[2];
#pragma unroll
    for (int mi = 0; mi < 2; mi++)
        aRow[mi] = (uint32_t)((m_off + mi * 16 + ar) * 128);
    const uint32_t aKad = (uint32_t)(ah * 16);
    const int l8 = lane & 7, sel = lane >> 3;
    const uint32_t bXor = (uint32_t)((l8 & 7) << 4);
    uint32_t bRow[4];
#pragma unroll
    for (int j = 0; j < 4; j++)
        bRow[j] = (uint32_t)((n_off + j * 16 + ((sel >> 1) * 8) + l8) * 128);
    const uint32_t bKad = (uint32_t)((sel & 1) * 16);

    float acc[2][8][4];
#pragma unroll
    for (int mi = 0; mi < 2; mi++)
#pragma unroll
        for (int nj = 0; nj < 8; nj++)
#pragma unroll
            for (int c = 0; c < 4; c++) acc[mi][nj][c] = 0.0f;

    auto load_chunk = [&](int c, int s) {
        const int k0 = c * BK;
        const uint32_t ab = sb + s * STAGE_BYTES;
        const uint32_t bb = ab + A_BYTES;
#pragma unroll
        for (int i = 0; i < 2; i++)
            cpa16(ab + doff + (uint32_t)(i * 8192), Ag + (size_t)(64 * i) * Kd + k0);
#pragma unroll
        for (int i = 0; i < 4; i++)
            cpa16(bb + doff + (uint32_t)(i * 8192), Bg + (size_t)(64 * i) * Kd + k0);
    };

    for (int s = 0; s < STAGES - 1; s++) {
        load_chunk(s, s);
        CP_COMMIT();
    }

    for (int it = 0; it < total; it++) {
        CP_WAIT2();
        __syncthreads();
        const int nc = it + STAGES - 1;
        if (nc < total) load_chunk(nc, nc % STAGES);
        CP_COMMIT();

        const int s = it % STAGES;
        const uint32_t ab = sb + s * STAGE_BYTES;
        const uint32_t bb = ab + A_BYTES;
#pragma unroll
        for (int ks = 0; ks < BK / 16; ks++) {
            uint32_t af[2][4];
            uint32_t bfr[8][2];
#pragma unroll
            for (int mi = 0; mi < 2; mi++)
                ldm4(af[mi], ab + aRow[mi] + (((uint32_t)(ks * 32) + aKad) ^ aXor));
#pragma unroll
            for (int j = 0; j < 4; j++) {
                uint32_t r[4];
                ldm4(r, bb + bRow[j] + (((uint32_t)(ks * 32) + bKad) ^ bXor));
                bfr[2 * j][0] = r[0]; bfr[2 * j][1] = r[1];
                bfr[2 * j + 1][0] = r[2]; bfr[2 * j + 1][1] = r[3];
            }
#pragma unroll
            for (int mi = 0; mi < 2; mi++)
#pragma unroll
                for (int nj = 0; nj < 8; nj++)
                    mma16816(acc[mi][nj], af[mi], bfr[nj]);
        }
    }

    // ---- epilogue ----
    const int crow = lane >> 2;
    const int ccol = (lane & 3) * 2;
#pragma unroll
    for (int nj = 0; nj < 8; nj++) {
        const int col = bn + n_off + nj * 8 + ccol;
        const float2 bb2 = *(const float2*)(bias + col);
#pragma unroll
        for (int mi = 0; mi < 2; mi++) {
            const int r0 = bm + m_off + mi * 16 + crow;
#pragma unroll
            for (int h = 0; h < 2; h++) {
                const int row = r0 + 8 * h;
                float v0 = acc[mi][nj][2 * h + 0] + bb2.x;
                float v1 = acc[mi][nj][2 * h + 1] + bb2.y;
                if (ACT == 1) { v0 = tanhf(v0); v1 = tanhf(v1); }
                else if (ACT == 2) { v0 = fmaxf(v0, 0.f); v1 = fmaxf(v1, 0.f); }
                if (OUTF32) {
                    float* dst = (float*)Cout + (size_t)bz * sC + (size_t)row * N + col;
                    *(float2*)dst = make_float2(v0, v1);
                } else {
                    __half2 hh = __halves2half2(__float2half_rn(v0), __float2half_rn(v1));
                    __half* base = (__half*)Cout + (size_t)bz * sC + (size_t)row * N + col;
                    *(uint32_t*)base = *(uint32_t*)&hh;
                }
            }
        }
    }
}

// ---------------------------------------------------------------------------
// Prep kernels
// ---------------------------------------------------------------------------
__global__ void xhalf(const float* __restrict__ x, __half* __restrict__ T0) {
    size_t i = (size_t)blockIdx.x * 256 + threadIdx.x;
    T0[i] = __float2half_rn(x[i]);
}

// W [K,N] fp32 -> WT [N,K] fp16
__global__ void wsplit(const float* __restrict__ W, __half* __restrict__ WT,
                       int Kd, int N, size_t sW, size_t sWT) {
    __shared__ float t[32][33];
    const int bz = blockIdx.z;
    W  += (size_t)bz * sW;
    WT += (size_t)bz * sWT;
    const int n0 = blockIdx.x * 32, k0 = blockIdx.y * 32;
    const int tx = threadIdx.x, ty = threadIdx.y;
    for (int i = 0; i < 32; i += 8)
        t[ty + i][tx] = W[(size_t)(k0 + ty + i) * N + n0 + tx];
    __syncthreads();
    for (int i = 0; i < 32; i += 8)
        WT[(size_t)(n0 + ty + i) * Kd + k0 + tx] = __float2half_rn(t[tx][ty + i]);
}

// ---------------------------------------------------------------------------
// Gram + normalize + score
// ---------------------------------------------------------------------------
__device__ __forceinline__ void pair_of(int p, int& i, int& j) {
    int ii = 0, rem = p;
    while (rem >= NV - ii) { rem -= NV - ii; ii++; }
    i = ii; j = ii + rem;
}
#define CHUNK 256
#define MAXP_PER_WARP 10

__global__ void gram_score(const float* __restrict__ Z, float* __restrict__ out) {
    __shared__ float chunk[NV][CHUNK];
    __shared__ float sG[NV * NV];
    const int b = blockIdx.x, tid = threadIdx.x;
    const int lane = tid & 31, warp = tid >> 5;

    int pi_i[MAXP_PER_WARP], pi_j[MAXP_PER_WARP];
    float accp[MAXP_PER_WARP];
#pragma unroll
    for (int pi = 0; pi < MAXP_PER_WARP; pi++) {
        int p = warp + pi * 8;
        if (p < NPAIR) pair_of(p, pi_i[pi], pi_j[pi]);
        else { pi_i[pi] = 0; pi_j[pi] = 0; }
        accp[pi] = 0.0f;
    }
    for (int h0 = 0; h0 < Hn; h0 += CHUNK) {
        __syncthreads();
        for (int i = tid; i < NV * (CHUNK / 4); i += 256) {
            int v = i / (CHUNK / 4);
            int h4 = (i % (CHUNK / 4)) * 4;
            float4 val = *(const float4*)(Z + (size_t)v * Bn * Hn + (size_t)b * Hn + h0 + h4);
            *(float4*)(&chunk[v][h4]) = val;
        }
        __syncthreads();
#pragma unroll
        for (int pi = 0; pi < MAXP_PER_WARP; pi++) {
            int p = warp + pi * 8;
            if (p < NPAIR) {
                const float* ri = chunk[pi_i[pi]];
                const float* rj = chunk[pi_j[pi]];
                float s = 0.0f;
#pragma unroll
                for (int t = 0; t < CHUNK / 32; t++)
                    s = fmaf(ri[lane + 32 * t], rj[lane + 32 * t], s);
                accp[pi] += s;
            }
        }
    }
#pragma unroll
    for (int pi = 0; pi < MAXP_PER_WARP; pi++) {
        int p = warp + pi * 8;
        if (p < NPAIR) {
            float s = accp[pi];
#pragma unroll
            for (int o = 16; o; o >>= 1) s += __shfl_xor_sync(0xffffffffu, s, o);
            if (lane == 0) {
                sG[pi_i[pi] * NV + pi_j[pi]] = s;
                sG[pi_j[pi] * NV + pi_i[pi]] = s;
            }
        }
    }
    __syncthreads();
    if (tid == 0) {
        float nm[NV];
#pragma unroll
        for (int i = 0; i < NV; i++) nm[i] = fmaxf(sqrtf(sG[i * NV + i]), EPSF);
        float total = 0.0f;
        for (int k = 1; k < NV; k++) {
            float pos = expf(sG[k] / (nm[0] * nm[k]));
            float neg = 0.0f;
            for (int l = 1; l < NV; l++)
                if (l != k) neg += expf(sG[k * NV + l] / (nm[k] * nm[l]));
            total += logf((pos + neg) / pos);
        }
        out[b] = total;
    }
}

// ---------------------------------------------------------------------------
// Launch
// ---------------------------------------------------------------------------
extern "C" void kernel_launch(void* const* d_in, const int* in_sizes, int n_in,
                              void* d_out, int out_size)
{
    const float* x   = (const float*)d_in[0];
    const float* Wt1 = (const float*)d_in[1];
    const float* bt1 = (const float*)d_in[2];
    const float* Wt2 = (const float*)d_in[3];
    const float* bt2 = (const float*)d_in[4];
    const float* We1 = (const float*)d_in[5];
    const float* be1 = (const float*)d_in[6];
    const float* We2 = (const float*)d_in[7];
    const float* be2 = (const float*)d_in[8];
    float* out = (float*)d_out;

    __half *T, *H, *WT1, *WT2, *WE1, *WE2;
    float* Z;
    cudaGetSymbolAddress((void**)&T, g_T);
    cudaGetSymbolAddress((void**)&H, g_H);
    cudaGetSymbolAddress((void**)&Z, g_Z);
    cudaGetSymbolAddress((void**)&WT1, g_WT1);
    cudaGetSymbolAddress((void**)&WT2, g_WT2);
    cudaGetSymbolAddress((void**)&WE1, g_WE1);
    cudaGetSymbolAddress((void**)&WE2, g_WE2);

    xhalf<<<(Bn * Dn) / 256, 256>>>(x, T);
    wsplit<<<dim3(Hn / 32, Dn / 32, KV), dim3(32, 8)>>>(
        Wt1, WT1, Dn, Hn, (size_t)Dn * Hn, (size_t)Hn * Dn);
    wsplit<<<dim3(Dn / 32, Hn / 32, KV), dim3(32, 8)>>>(
        Wt2, WT2, Hn, Dn, (size_t)Hn * Dn, (size_t)Dn * Hn);
    wsplit<<<dim3(Hn / 32, Dn / 32, 1), dim3(32, 8)>>>(We1, WE1, Dn, Hn, 0, 0);
    wsplit<<<dim3(Hn / 32, Hn / 32, 1), dim3(32, 8)>>>(We2, WE2, Hn, Hn, 0, 0);

    cudaFuncSetAttribute(gemm_mma<1, 0>, cudaFuncAttributeMaxDynamicSharedMemorySize, GEMM_SMEM);
    cudaFuncSetAttribute(gemm_mma<0, 0>, cudaFuncAttributeMaxDynamicSharedMemorySize, GEMM_SMEM);
    cudaFuncSetAttribute(gemm_mma<2, 0>, cudaFuncAttributeMaxDynamicSharedMemorySize, GEMM_SMEM);
    cudaFuncSetAttribute(gemm_mma<0, 1>, cudaFuncAttributeMaxDynamicSharedMemorySize, GEMM_SMEM);

    // A1: H[k] = tanh(x @ Wt1[k] + bt1[k])
    gemm_mma<1, 0><<<dim3(Hn / TILE_N, Bn / TILE_M, KV), 512, GEMM_SMEM>>>(
        T, WT1, bt1, H, Hn, Dn,
        (size_t)0, (size_t)Hn * Dn, (size_t)Hn, (size_t)Bn * Hn);

    // A2: T[1+k] = H[k] @ Wt2[k] + bt2[k]
    gemm_mma<0, 0><<<dim3(Dn / TILE_N, Bn / TILE_M, KV), 512, GEMM_SMEM>>>(
        H, WT2, bt2, T + (size_t)Bn * Dn, Dn, Hn,
        (size_t)Bn * Hn, (size_t)Dn * Hn, (size_t)Dn, (size_t)Bn * Dn);

    // B1: H[v] = relu(T[v] @ We1 + be1)
    gemm_mma<2, 0><<<dim3(Hn / TILE_N, Bn / TILE_M, NV), 512, GEMM_SMEM>>>(
        T, WE1, be1, H, Hn, Dn,
        (size_t)Bn * Dn, (size_t)0, (size_t)0, (size_t)Bn * Hn);

    // B2: Z[v] = H[v] @ We2 + be2  (fp32 out)
    gemm_mma<0, 1><<<dim3(Hn / TILE_N, Bn / TILE_M, NV), 512, GEMM_SMEM>>>(
        H, WE2, be2, Z, Hn, Hn,
        (size_t)Bn * Hn, (size_t)0, (size_t)0, (size_t)Bn * Hn);

    gram_score<<<Bn, 256>>>(Z, out);
}